// round 2
// baseline (speedup 1.0000x reference)
#include <cuda_runtime.h>
#include <cuda_bf16.h>
#include <math.h>

// Problem dims
#define BB   16
#define CC   192
#define HW   2304          // 48*48
#define NTOT (BB*HW)       // 36864

// ------------------------------------------------------------------
// Scratch (device globals -- allocation-free rule)
// ------------------------------------------------------------------
__device__ float g_xn[(size_t)NTOT * CC];      // xn, later reused as attn@V output
__device__ float g_q [(size_t)NTOT * CC];
__device__ float g_k [(size_t)NTOT * CC];
__device__ float g_v [(size_t)NTOT * CC];
__device__ float g_s [(size_t)BB * HW * HW];   // 340 MB scores

// ------------------------------------------------------------------
// K1: LayerNorm over C with [B,C,HW] -> [B,N,C] transpose
// block: 256 threads, 32 spatial positions
// ------------------------------------------------------------------
__global__ __launch_bounds__(256) void ln_transpose_kernel(
    const float* __restrict__ x,
    const float* __restrict__ ln_w,
    const float* __restrict__ ln_b,
    float* __restrict__ xn)
{
    __shared__ float tile[CC][33];
    __shared__ float part_s[8][32];
    __shared__ float part_q[8][32];
    __shared__ float s_mu[32], s_ri[32];

    const int b  = blockIdx.y;
    const int n0 = blockIdx.x * 32;
    const int tid = threadIdx.x;
    const int n   = tid & 31;
    const int g   = tid >> 5;          // 0..7

    const float* xb = x + (size_t)b * CC * HW;

    // load [192 x 32] tile, coalesced over n
    #pragma unroll
    for (int i = 0; i < 24; i++) {
        int c = g + 8 * i;
        tile[c][n] = xb[(size_t)c * HW + n0 + n];
    }
    __syncthreads();

    // per-column stats: 8 partials per column
    float s = 0.f, q = 0.f;
    #pragma unroll
    for (int j = 0; j < 24; j++) {
        float v = tile[g + 8 * j][n];
        s += v; q += v * v;
    }
    part_s[g][n] = s;
    part_q[g][n] = q;
    __syncthreads();

    if (tid < 32) {
        float ts = 0.f, tq = 0.f;
        #pragma unroll
        for (int j = 0; j < 8; j++) { ts += part_s[j][tid]; tq += part_q[j][tid]; }
        float mu  = ts * (1.0f / CC);
        float var = tq * (1.0f / CC) - mu * mu;
        s_mu[tid] = mu;
        s_ri[tid] = rsqrtf(var + 1e-5f);
    }
    __syncthreads();

    // write xn[b, n, c], coalesced over c
    #pragma unroll
    for (int i = 0; i < 24; i++) {
        int j  = tid + 256 * i;            // 0..6143
        int c  = j % CC;
        int nn = j / CC;
        float v = (tile[c][nn] - s_mu[nn]) * s_ri[nn] * ln_w[c] + ln_b[c];
        xn[((size_t)(b * HW + n0 + nn)) * CC + c] = v;
    }
}

// ------------------------------------------------------------------
// SGEMM: C[m,n] = sum_k A[m,k] * B'[k,n]
//   B_K_MAJOR = true : B stored [n, k] (k contiguous)  -> dot-product GEMM
//   B_K_MAJOR = false: B stored [k, n] (n contiguous)
// Block tile 128(M) x 64(N), K-step 16, 256 threads, 8x4 microtile.
// ------------------------------------------------------------------
template<bool B_K_MAJOR>
__global__ __launch_bounds__(256) void gemm_kernel(
    const float* __restrict__ A, const float* __restrict__ B,
    float* __restrict__ C,
    int K, int lda, int ldb, int ldc,
    size_t strideA, size_t strideB, size_t strideC)
{
    __shared__ float As[16][132];
    __shared__ float Bs[16][68];

    const float* Ab = A + (size_t)blockIdx.z * strideA;
    const float* Bb = B + (size_t)blockIdx.z * strideB;
    float*       Cb = C + (size_t)blockIdx.z * strideC;

    const int tid = threadIdx.x;
    const int tx  = tid & 15;           // 0..15  -> N
    const int ty  = tid >> 4;           // 0..15  -> M
    const int m0  = blockIdx.x * 128;
    const int n0  = blockIdx.y * 64;

    float acc[8][4];
    #pragma unroll
    for (int i = 0; i < 8; i++)
        #pragma unroll
        for (int j = 0; j < 4; j++) acc[i][j] = 0.f;

    const int kk = (tid & 3) * 4;       // 0,4,8,12
    const int rA = tid >> 2;            // 0..63

    for (int k0 = 0; k0 < K; k0 += 16) {
        // A tile -> As[k][m] (transposed store)
        #pragma unroll
        for (int i = 0; i < 2; i++) {
            int m = rA + i * 64;
            float4 v = *(const float4*)&Ab[(size_t)(m0 + m) * lda + k0 + kk];
            As[kk + 0][m] = v.x; As[kk + 1][m] = v.y;
            As[kk + 2][m] = v.z; As[kk + 3][m] = v.w;
        }
        // B tile -> Bs[k][n]
        if (B_K_MAJOR) {
            int nr = rA;                // 0..63
            float4 v = *(const float4*)&Bb[(size_t)(n0 + nr) * ldb + k0 + kk];
            Bs[kk + 0][nr] = v.x; Bs[kk + 1][nr] = v.y;
            Bs[kk + 2][nr] = v.z; Bs[kk + 3][nr] = v.w;
        } else {
            int kr = tid >> 4;          // 0..15
            int nn = (tid & 15) * 4;    // 0..60
            float4 v = *(const float4*)&Bb[(size_t)(k0 + kr) * ldb + n0 + nn];
            *(float4*)&Bs[kr][nn] = v;
        }
        __syncthreads();

        #pragma unroll
        for (int k = 0; k < 16; k++) {
            float4 a0 = *(const float4*)&As[k][ty * 8];
            float4 a1 = *(const float4*)&As[k][ty * 8 + 4];
            float4 b0 = *(const float4*)&Bs[k][tx * 4];
            float a[8] = {a0.x, a0.y, a0.z, a0.w, a1.x, a1.y, a1.z, a1.w};
            float bv[4] = {b0.x, b0.y, b0.z, b0.w};
            #pragma unroll
            for (int i = 0; i < 8; i++)
                #pragma unroll
                for (int j = 0; j < 4; j++)
                    acc[i][j] = fmaf(a[i], bv[j], acc[i][j]);
        }
        __syncthreads();
    }

    #pragma unroll
    for (int i = 0; i < 8; i++) {
        int m = m0 + ty * 8 + i;
        float4 v = make_float4(acc[i][0], acc[i][1], acc[i][2], acc[i][3]);
        *(float4*)&Cb[(size_t)m * ldc + n0 + tx * 4] = v;
    }
}

// ------------------------------------------------------------------
// K4: per-row blend  S <- a1*softmax(S) + a2*relu(S)^2
// one block (256 threads) per row of 2304
// ------------------------------------------------------------------
__global__ __launch_bounds__(256) void blend_kernel(
    float* __restrict__ S,
    const float* __restrict__ w1,
    const float* __restrict__ w2)
{
    __shared__ float red[256];
    float* row = S + (size_t)blockIdx.x * HW;
    const int tid = threadIdx.x;

    float v[9];
    #pragma unroll
    for (int i = 0; i < 9; i++) v[i] = row[tid + 256 * i];

    // row max
    float m = v[0];
    #pragma unroll
    for (int i = 1; i < 9; i++) m = fmaxf(m, v[i]);
    red[tid] = m; __syncthreads();
    for (int s = 128; s > 0; s >>= 1) {
        if (tid < s) red[tid] = fmaxf(red[tid], red[tid + s]);
        __syncthreads();
    }
    const float m_all = red[0];
    __syncthreads();

    // exp + row sum
    float e[9];
    float l = 0.f;
    #pragma unroll
    for (int i = 0; i < 9; i++) { e[i] = expf(v[i] - m_all); l += e[i]; }
    red[tid] = l; __syncthreads();
    for (int s = 128; s > 0; s >>= 1) {
        if (tid < s) red[tid] += red[tid + s];
        __syncthreads();
    }
    const float l_all = red[0];

    const float e1 = expf(w1[0]);
    const float e2 = expf(w2[0]);
    const float inv = 1.0f / (e1 + e2);
    const float a1 = e1 * inv, a2 = e2 * inv;
    const float sc = a1 / l_all;

    #pragma unroll
    for (int i = 0; i < 9; i++) {
        float r = fmaxf(v[i], 0.f);
        row[tid + 256 * i] = e[i] * sc + a2 * r * r;
    }
}

// ------------------------------------------------------------------
// K6: [B,N,C] -> [B,C,H,W] transpose + residual
// ------------------------------------------------------------------
__global__ __launch_bounds__(256) void out_transpose_kernel(
    const float* __restrict__ obnd,
    const float* __restrict__ x,
    float* __restrict__ out)
{
    __shared__ float tile[32][33];
    const int b  = blockIdx.z;
    const int n0 = blockIdx.x * 32;
    const int c0 = blockIdx.y * 32;
    const int tid = threadIdx.x;
    const int a = tid & 31;        // fast index
    const int g = tid >> 5;        // 0..7

    #pragma unroll
    for (int i = 0; i < 4; i++) {
        int nn = g + 8 * i;
        tile[nn][a] = obnd[((size_t)(b * HW + n0 + nn)) * CC + c0 + a];
    }
    __syncthreads();
    #pragma unroll
    for (int i = 0; i < 4; i++) {
        int c = g + 8 * i;
        size_t idx = ((size_t)(b * CC + c0 + c)) * HW + n0 + a;
        out[idx] = tile[a][c] + x[idx];
    }
}

// ------------------------------------------------------------------
// launch
// ------------------------------------------------------------------
extern "C" void kernel_launch(void* const* d_in, const int* in_sizes, int n_in,
                              void* d_out, int out_size)
{
    (void)in_sizes; (void)n_in; (void)out_size;
    const float* x    = (const float*)d_in[0];
    const float* ln_w = (const float*)d_in[1];
    const float* ln_b = (const float*)d_in[2];
    const float* Wq   = (const float*)d_in[3];
    const float* Wk   = (const float*)d_in[4];
    const float* Wv   = (const float*)d_in[5];
    const float* w1   = (const float*)d_in[6];
    const float* w2   = (const float*)d_in[7];
    float* out = (float*)d_out;

    float *xn, *q, *k, *v, *s;
    cudaGetSymbolAddress((void**)&xn, g_xn);
    cudaGetSymbolAddress((void**)&q,  g_q);
    cudaGetSymbolAddress((void**)&k,  g_k);
    cudaGetSymbolAddress((void**)&v,  g_v);
    cudaGetSymbolAddress((void**)&s,  g_s);

    // K1: LN + transpose
    ln_transpose_kernel<<<dim3(HW / 32, BB), 256>>>(x, ln_w, ln_b, xn);

    // K2: Q/K/V projections (M=36864, N=192, K=192), W is [d, c] k-major
    {
        dim3 grid(NTOT / 128, CC / 64, 1);
        gemm_kernel<true><<<grid, 256>>>(xn, Wq, q, CC, CC, CC, CC, 0, 0, 0);
        gemm_kernel<true><<<grid, 256>>>(xn, Wk, k, CC, CC, CC, CC, 0, 0, 0);
        gemm_kernel<true><<<grid, 256>>>(xn, Wv, v, CC, CC, CC, CC, 0, 0, 0);
    }

    // K3: S = Q @ K^T per batch (M=N=2304, K=192)
    {
        dim3 grid(HW / 128, HW / 64, BB);
        gemm_kernel<true><<<grid, 256>>>(q, k, s, CC, CC, CC, HW,
                                         (size_t)HW * CC, (size_t)HW * CC,
                                         (size_t)HW * HW);
    }

    // K4: blend softmax + relu^2
    blend_kernel<<<dim3(NTOT), 256>>>(s, w1, w2);

    // K5: out_bnd = attn @ V per batch (M=2304, N=192, K=2304), V is n-major
    {
        dim3 grid(HW / 128, CC / 64, BB);
        gemm_kernel<false><<<grid, 256>>>(s, v, xn, HW, HW, CC, CC,
                                          (size_t)HW * HW, (size_t)HW * CC,
                                          (size_t)HW * CC);
    }

    // K6: transpose back + residual
    out_transpose_kernel<<<dim3(HW / 32, CC / 32, BB), 256>>>(xn, x, out);
}

// round 4
// speedup vs baseline: 1.9403x; 1.9403x over previous
#include <cuda_runtime.h>
#include <cuda_bf16.h>
#include <math.h>
#include <stdint.h>

using bf16 = __nv_bfloat16;

// Problem dims
#define BB   16
#define CC   192
#define HW   2304          // 48*48
#define NTOT (BB*HW)       // 36864

// GEMM tiling
#define BM 128
#define BN 64
#define BK 32
#define ST 40              // smem row stride in halves (80B: conflict-free ldmatrix)
#define STAGE_H (384*ST)   // halves per stage: (128+128+64+64) rows * ST
#define SMEM_BYTES (2*STAGE_H*2)   // 61440

// ------------------------------------------------------------------
// Scratch (device globals -- allocation-free rule)
// ------------------------------------------------------------------
__device__ bf16  g_xn_h[(size_t)NTOT * CC];
__device__ bf16  g_xn_l[(size_t)NTOT * CC];
__device__ bf16  g_q_h [(size_t)NTOT * CC];
__device__ bf16  g_q_l [(size_t)NTOT * CC];
__device__ bf16  g_k_h [(size_t)NTOT * CC];
__device__ bf16  g_k_l [(size_t)NTOT * CC];
__device__ bf16  g_vt_h[(size_t)CC * NTOT];    // [192, 36864] (d-major)
__device__ bf16  g_vt_l[(size_t)CC * NTOT];
__device__ bf16  g_w_h [(size_t)3 * CC * CC];
__device__ bf16  g_w_l [(size_t)3 * CC * CC];
__device__ float g_s   [(size_t)BB * HW * HW]; // scores fp32, then attn hi/lo in place
__device__ float g_o   [(size_t)NTOT * CC];    // attn @ V output [m, d] fp32

// ------------------------------------------------------------------
// helpers
// ------------------------------------------------------------------
__device__ __forceinline__ uint32_t smem_to_u32(const void* p) {
    uint32_t a;
    asm("{ .reg .u64 t; cvta.to.shared.u64 t, %1; cvt.u32.u64 %0, t; }"
        : "=r"(a) : "l"(p));
    return a;
}

#define CP_ASYNC16(saddr, gptr) \
    asm volatile("cp.async.cg.shared.global [%0], [%1], 16;" \
        :: "r"(saddr), "l"(gptr) : "memory")
#define CP_COMMIT() asm volatile("cp.async.commit_group;" ::: "memory")
#define CP_WAIT1()  asm volatile("cp.async.wait_group 1;" ::: "memory")
#define CP_WAIT0()  asm volatile("cp.async.wait_group 0;" ::: "memory")

__device__ __forceinline__ void ldsm_x4(uint32_t addr, uint32_t& r0, uint32_t& r1,
                                        uint32_t& r2, uint32_t& r3) {
    asm volatile("ldmatrix.sync.aligned.m8n8.x4.shared.b16 {%0,%1,%2,%3}, [%4];"
        : "=r"(r0), "=r"(r1), "=r"(r2), "=r"(r3) : "r"(addr));
}

__device__ __forceinline__ void mma_bf16(float* d, const uint32_t* a, const uint32_t* b) {
    asm volatile(
        "mma.sync.aligned.m16n8k16.row.col.f32.bf16.bf16.f32 "
        "{%0,%1,%2,%3}, {%4,%5,%6,%7}, {%8,%9}, {%0,%1,%2,%3};"
        : "+f"(d[0]), "+f"(d[1]), "+f"(d[2]), "+f"(d[3])
        : "r"(a[0]), "r"(a[1]), "r"(a[2]), "r"(a[3]), "r"(b[0]), "r"(b[1]));
}

__device__ __forceinline__ void split_bf16(float v, bf16& h, bf16& l) {
    h = __float2bfloat16_rn(v);
    l = __float2bfloat16_rn(v - __bfloat162float(h));
}
__device__ __forceinline__ uint32_t pack2(float v0, float v1, bf16& l0, bf16& l1) {
    bf16 h0, h1;
    split_bf16(v0, h0, l0);
    split_bf16(v1, h1, l1);
    uint32_t u;
    asm("mov.b32 %0, {%1, %2};" : "=r"(u) : "h"(*(uint16_t*)&h0), "h"(*(uint16_t*)&h1));
    return u;
}

// ------------------------------------------------------------------
// K1: LayerNorm over C with [B,C,HW] -> [B,N,C], split hi/lo bf16
// ------------------------------------------------------------------
__global__ __launch_bounds__(256) void ln_transpose_kernel(
    const float* __restrict__ x,
    const float* __restrict__ ln_w,
    const float* __restrict__ ln_b,
    bf16* __restrict__ xn_h, bf16* __restrict__ xn_l)
{
    __shared__ float tile[CC][33];
    __shared__ float part_s[8][32];
    __shared__ float part_q[8][32];
    __shared__ float s_mu[32], s_ri[32];

    const int b  = blockIdx.y;
    const int n0 = blockIdx.x * 32;
    const int tid = threadIdx.x;
    const int n   = tid & 31;
    const int g   = tid >> 5;

    const float* xb = x + (size_t)b * CC * HW;

    #pragma unroll
    for (int i = 0; i < 24; i++) {
        int c = g + 8 * i;
        tile[c][n] = xb[(size_t)c * HW + n0 + n];
    }
    __syncthreads();

    float s = 0.f, q = 0.f;
    #pragma unroll
    for (int j = 0; j < 24; j++) {
        float v = tile[g + 8 * j][n];
        s += v; q += v * v;
    }
    part_s[g][n] = s;
    part_q[g][n] = q;
    __syncthreads();

    if (tid < 32) {
        float ts = 0.f, tq = 0.f;
        #pragma unroll
        for (int j = 0; j < 8; j++) { ts += part_s[j][tid]; tq += part_q[j][tid]; }
        float mu  = ts * (1.0f / CC);
        float var = tq * (1.0f / CC) - mu * mu;
        s_mu[tid] = mu;
        s_ri[tid] = rsqrtf(var + 1e-5f);
    }
    __syncthreads();

    #pragma unroll
    for (int i = 0; i < 24; i++) {
        int j  = tid + 256 * i;
        int c  = j % CC;
        int nn = j / CC;
        float v = (tile[c][nn] - s_mu[nn]) * s_ri[nn] * ln_w[c] + ln_b[c];
        bf16 h, l; split_bf16(v, h, l);
        size_t o = ((size_t)(b * HW + n0 + nn)) * CC + c;
        xn_h[o] = h; xn_l[o] = l;
    }
}

// ------------------------------------------------------------------
// Weight split kernel
// ------------------------------------------------------------------
__global__ __launch_bounds__(256) void wsplit_kernel(
    const float* __restrict__ Wq, const float* __restrict__ Wk,
    const float* __restrict__ Wv,
    bf16* __restrict__ wh, bf16* __restrict__ wl)
{
    int i = blockIdx.x * 256 + threadIdx.x;
    if (i >= 3 * CC * CC) return;
    int wsel = i / (CC * CC);
    int j    = i % (CC * CC);
    const float* W = (wsel == 0) ? Wq : (wsel == 1) ? Wk : Wv;
    bf16 h, l; split_bf16(W[j], h, l);
    wh[i] = h; wl[i] = l;
}

// ------------------------------------------------------------------
// bf16x3 GEMM via mma.sync: C[m,n] = sum_k A[m,k]*B[n,k]
//   C = Ah*Bh + Ah*Bl + Al*Bh  (fp32 accumulate)
// 128x64 block tile, BK=32, 8 warps (4x2), warp tile 32x32.
// cp.async double-buffered.
// MODE: 0 = fp32 row-major out; 1 = hi/lo bf16 row-major;
//       2 = hi/lo bf16 transposed out (C[n][m], row stride ldc over m)
// ------------------------------------------------------------------
template<int MODE>
__global__ __launch_bounds__(256) void gemm_bf16x3(
    const bf16* __restrict__ Ah, const bf16* __restrict__ Al, int lda, size_t sA,
    const bf16* __restrict__ Bh, const bf16* __restrict__ Bl, int ldb, size_t sB,
    float* __restrict__ Cf, bf16* __restrict__ Ch, bf16* __restrict__ Cl,
    int ldc, size_t sC, int K)
{
    extern __shared__ char smem[];
    bf16* sm = (bf16*)smem;
    const uint32_t sb = smem_to_u32(smem);

    const int tid  = threadIdx.x;
    const int wid  = tid >> 5;
    const int lane = tid & 31;
    const int wm   = wid & 3;     // 0..3  -> M (32 rows each)
    const int wn   = wid >> 2;    // 0..1  -> N (32 cols each)
    const int m0   = blockIdx.x * BM;
    const int n0   = blockIdx.y * BN;
    const int b    = blockIdx.z;

    Ah += (size_t)b * sA; Al += (size_t)b * sA;
    Bh += (size_t)b * sB; Bl += (size_t)b * sB;

    // ---- global->smem slot mapping (6 slots of 256 uint4) ----
    const bf16* gbase[6];
    uint32_t    soff[6];          // halves offset within one stage
    #pragma unroll
    for (int s = 0; s < 6; s++) {
        int idx = s * 256 + tid;
        if (idx < 1024) {                       // A region (hi, lo)
            int arr = idx >> 9;
            int r   = (idx >> 2) & 127;
            int qd  = idx & 3;
            gbase[s] = (arr ? Al : Ah) + (size_t)(m0 + r) * lda + qd * 8;
            soff[s]  = arr * 128 * ST + r * ST + qd * 8;
        } else {                                // B region (hi, lo)
            int j   = idx - 1024;
            int arr = j >> 8;
            int r   = (j >> 2) & 63;
            int qd  = j & 3;
            gbase[s] = (arr ? Bl : Bh) + (size_t)(n0 + r) * ldb + qd * 8;
            soff[s]  = 256 * ST + arr * 64 * ST + r * ST + qd * 8;
        }
    }

    // ldmatrix lane addressing (halves offsets within a stage)
    //   A tiles: rows wm*32 + mt*16; addr row = +(lane&15), col = (lane>>4)*8
    const int a_row = wm * 32 + (lane & 15);
    const int a_col = (lane >> 4) << 3;
    //   B tiles: rows wn*32 + nt2*16 + ((lane>>4)<<3) + (lane&7), col = ((lane>>3)&1)*8
    const int b_row = wn * 32 + ((lane >> 4) << 3) + (lane & 7);
    const int b_col = ((lane >> 3) & 1) << 3;

    float acc[2][4][4];
    #pragma unroll
    for (int i = 0; i < 2; i++)
        #pragma unroll
        for (int j = 0; j < 4; j++)
            #pragma unroll
            for (int t = 0; t < 4; t++) acc[i][j][t] = 0.f;

    const int nc = K >> 5;       // BK=32 chunks

    // prologue: chunk 0
    #pragma unroll
    for (int s = 0; s < 6; s++)
        CP_ASYNC16(sb + 2 * soff[s], gbase[s]);
    CP_COMMIT();

    for (int c = 0; c < nc; c++) {
        if (c + 1 < nc) {
            const int st = (c + 1) & 1;
            const int k0 = (c + 1) << 5;
            #pragma unroll
            for (int s = 0; s < 6; s++)
                CP_ASYNC16(sb + 2 * (st * STAGE_H + soff[s]), gbase[s] + k0);
            CP_COMMIT();
            CP_WAIT1();
        } else {
            CP_WAIT0();
        }
        __syncthreads();

        const uint32_t stg = (c & 1) * STAGE_H;
        const uint32_t sAh = sb + 2 * (stg + 0);
        const uint32_t sAl = sb + 2 * (stg + 128 * ST);
        const uint32_t sBh = sb + 2 * (stg + 256 * ST);
        const uint32_t sBl = sb + 2 * (stg + 320 * ST);

        #pragma unroll
        for (int ks = 0; ks < 2; ks++) {
            const int kof = ks * 16;
            uint32_t ah[2][4], al[2][4], bh[2][4], bl[2][4];
            #pragma unroll
            for (int mt = 0; mt < 2; mt++) {
                uint32_t off = 2 * ((a_row + mt * 16) * ST + kof + a_col);
                ldsm_x4(sAh + off, ah[mt][0], ah[mt][1], ah[mt][2], ah[mt][3]);
                ldsm_x4(sAl + off, al[mt][0], al[mt][1], al[mt][2], al[mt][3]);
            }
            #pragma unroll
            for (int nt2 = 0; nt2 < 2; nt2++) {
                uint32_t off = 2 * ((b_row + nt2 * 16) * ST + kof + b_col);
                ldsm_x4(sBh + off, bh[nt2][0], bh[nt2][1], bh[nt2][2], bh[nt2][3]);
                ldsm_x4(sBl + off, bl[nt2][0], bl[nt2][1], bl[nt2][2], bl[nt2][3]);
            }
            #pragma unroll
            for (int mt = 0; mt < 2; mt++) {
                #pragma unroll
                for (int nt = 0; nt < 4; nt++) {
                    const uint32_t* bph = &bh[nt >> 1][(nt & 1) * 2];
                    const uint32_t* bpl = &bl[nt >> 1][(nt & 1) * 2];
                    mma_bf16(acc[mt][nt], ah[mt], bph);   // Ah*Bh
                    mma_bf16(acc[mt][nt], ah[mt], bpl);   // Ah*Bl
                    mma_bf16(acc[mt][nt], al[mt], bph);   // Al*Bh
                }
            }
        }
        __syncthreads();
    }

    // ---- epilogue: stage to smem fp32 tile [128][65], then write ----
    float* tile = (float*)smem;
    const int tr = lane >> 2;          // 0..7
    const int tc = (lane & 3) * 2;     // 0,2,4,6
    #pragma unroll
    for (int mt = 0; mt < 2; mt++) {
        #pragma unroll
        for (int nt = 0; nt < 4; nt++) {
            int rbase = wm * 32 + mt * 16 + tr;
            int cbase = wn * 32 + nt * 8 + tc;
            tile[rbase * 65 + cbase]            = acc[mt][nt][0];
            tile[rbase * 65 + cbase + 1]        = acc[mt][nt][1];
            tile[(rbase + 8) * 65 + cbase]      = acc[mt][nt][2];
            tile[(rbase + 8) * 65 + cbase + 1]  = acc[mt][nt][3];
        }
    }
    __syncthreads();

    if (MODE == 0) {
        Cf += (size_t)b * sC;
        #pragma unroll
        for (int it = 0; it < 8; it++) {
            int idx = tid + 256 * it;          // 2048 float4
            int r = idx >> 4, q = idx & 15;
            float4 v = make_float4(tile[r * 65 + q * 4], tile[r * 65 + q * 4 + 1],
                                   tile[r * 65 + q * 4 + 2], tile[r * 65 + q * 4 + 3]);
            *(float4*)&Cf[(size_t)(m0 + r) * ldc + n0 + q * 4] = v;
        }
    } else if (MODE == 1) {
        #pragma unroll
        for (int it = 0; it < 16; it++) {
            int idx = tid + 256 * it;          // 4096 pairs
            int r = idx >> 5, p = idx & 31;
            bf16 l0, l1;
            uint32_t hu = pack2(tile[r * 65 + 2 * p], tile[r * 65 + 2 * p + 1], l0, l1);
            uint32_t lu;
            asm("mov.b32 %0, {%1, %2};" : "=r"(lu)
                : "h"(*(uint16_t*)&l0), "h"(*(uint16_t*)&l1));
            size_t o = (size_t)(m0 + r) * ldc + n0 + 2 * p;
            *(uint32_t*)&Ch[o] = hu;
            *(uint32_t*)&Cl[o] = lu;
        }
    } else {  // MODE 2: transposed out C[n][m]
        #pragma unroll
        for (int it = 0; it < 16; it++) {
            int idx = tid + 256 * it;          // 64 rows x 64 pairs
            int r = idx >> 6, p = idx & 63;    // r = n_local, p = m pair
            bf16 l0, l1;
            uint32_t hu = pack2(tile[(2 * p) * 65 + r], tile[(2 * p + 1) * 65 + r], l0, l1);
            uint32_t lu;
            asm("mov.b32 %0, {%1, %2};" : "=r"(lu)
                : "h"(*(uint16_t*)&l0), "h"(*(uint16_t*)&l1));
            size_t o = (size_t)(n0 + r) * ldc + m0 + 2 * p;
            *(uint32_t*)&Ch[o] = hu;
            *(uint32_t*)&Cl[o] = lu;
        }
    }
}

// ------------------------------------------------------------------
// K4: per-row blend; read fp32 S row, write bf16 hi/lo attn in place
// ------------------------------------------------------------------
__global__ __launch_bounds__(256) void blend_kernel(
    float* __restrict__ S,
    const float* __restrict__ w1,
    const float* __restrict__ w2)
{
    __shared__ float red[256];
    float* row = S + (size_t)blockIdx.x * HW;
    const int tid = threadIdx.x;

    float v[9];
    #pragma unroll
    for (int i = 0; i < 9; i++) v[i] = row[tid + 256 * i];

    float m = v[0];
    #pragma unroll
    for (int i = 1; i < 9; i++) m = fmaxf(m, v[i]);
    red[tid] = m; __syncthreads();
    for (int s = 128; s > 0; s >>= 1) {
        if (tid < s) red[tid] = fmaxf(red[tid], red[tid + s]);
        __syncthreads();
    }
    const float m_all = red[0];
    __syncthreads();

    float e[9];
    float l = 0.f;
    #pragma unroll
    for (int i = 0; i < 9; i++) { e[i] = expf(v[i] - m_all); l += e[i]; }
    red[tid] = l; __syncthreads();
    for (int s = 128; s > 0; s >>= 1) {
        if (tid < s) red[tid] += red[tid + s];
        __syncthreads();
    }
    const float l_all = red[0];
    __syncthreads();   // everyone done reading row before in-place overwrite

    const float e1 = expf(w1[0]);
    const float e2 = expf(w2[0]);
    const float inv = 1.0f / (e1 + e2);
    const float a1 = e1 * inv, a2 = e2 * inv;
    const float sc = a1 / l_all;

    bf16* rh = (bf16*)row;
    bf16* rl = rh + HW;

    #pragma unroll
    for (int i = 0; i < 9; i++) {
        float r = fmaxf(v[i], 0.f);
        float val = e[i] * sc + a2 * r * r;
        bf16 h, lo; split_bf16(val, h, lo);
        rh[tid + 256 * i] = h;
        rl[tid + 256 * i] = lo;
    }
}

// ------------------------------------------------------------------
// K6: [B,N,C] -> [B,C,H,W] transpose + residual
// ------------------------------------------------------------------
__global__ __launch_bounds__(256) void out_transpose_kernel(
    const float* __restrict__ obnd,
    const float* __restrict__ x,
    float* __restrict__ out)
{
    __shared__ float tile[32][33];
    const int b  = blockIdx.z;
    const int n0 = blockIdx.x * 32;
    const int c0 = blockIdx.y * 32;
    const int tid = threadIdx.x;
    const int a = tid & 31;
    const int g = tid >> 5;

    #pragma unroll
    for (int i = 0; i < 4; i++) {
        int nn = g + 8 * i;
        tile[nn][a] = obnd[((size_t)(b * HW + n0 + nn)) * CC + c0 + a];
    }
    __syncthreads();
    #pragma unroll
    for (int i = 0; i < 4; i++) {
        int c = g + 8 * i;
        size_t idx = ((size_t)(b * CC + c0 + c)) * HW + n0 + a;
        out[idx] = tile[a][c] + x[idx];
    }
}

// ------------------------------------------------------------------
// launch
// ------------------------------------------------------------------
extern "C" void kernel_launch(void* const* d_in, const int* in_sizes, int n_in,
                              void* d_out, int out_size)
{
    (void)in_sizes; (void)n_in; (void)out_size;
    const float* x    = (const float*)d_in[0];
    const float* ln_w = (const float*)d_in[1];
    const float* ln_b = (const float*)d_in[2];
    const float* Wq   = (const float*)d_in[3];
    const float* Wk   = (const float*)d_in[4];
    const float* Wv   = (const float*)d_in[5];
    const float* w1   = (const float*)d_in[6];
    const float* w2   = (const float*)d_in[7];
    float* out = (float*)d_out;

    bf16 *xn_h, *xn_l, *q_h, *q_l, *k_h, *k_l, *vt_h, *vt_l, *w_h, *w_l;
    float *s, *o;
    cudaGetSymbolAddress((void**)&xn_h, g_xn_h);
    cudaGetSymbolAddress((void**)&xn_l, g_xn_l);
    cudaGetSymbolAddress((void**)&q_h,  g_q_h);
    cudaGetSymbolAddress((void**)&q_l,  g_q_l);
    cudaGetSymbolAddress((void**)&k_h,  g_k_h);
    cudaGetSymbolAddress((void**)&k_l,  g_k_l);
    cudaGetSymbolAddress((void**)&vt_h, g_vt_h);
    cudaGetSymbolAddress((void**)&vt_l, g_vt_l);
    cudaGetSymbolAddress((void**)&w_h,  g_w_h);
    cudaGetSymbolAddress((void**)&w_l,  g_w_l);
    cudaGetSymbolAddress((void**)&s,    g_s);
    cudaGetSymbolAddress((void**)&o,    g_o);

    cudaFuncSetAttribute(gemm_bf16x3<0>, cudaFuncAttributeMaxDynamicSharedMemorySize, SMEM_BYTES);
    cudaFuncSetAttribute(gemm_bf16x3<1>, cudaFuncAttributeMaxDynamicSharedMemorySize, SMEM_BYTES);
    cudaFuncSetAttribute(gemm_bf16x3<2>, cudaFuncAttributeMaxDynamicSharedMemorySize, SMEM_BYTES);

    // K1: LN + transpose + split
    ln_transpose_kernel<<<dim3(HW / 32, BB), 256>>>(x, ln_w, ln_b, xn_h, xn_l);

    // Weight split
    wsplit_kernel<<<(3 * CC * CC + 255) / 256, 256>>>(Wq, Wk, Wv, w_h, w_l);

    // K2: Q, K projections (M=36864, N=192, K=192)
    {
        dim3 grid(NTOT / BM, CC / BN, 1);
        gemm_bf16x3<1><<<grid, 256, SMEM_BYTES>>>(
            xn_h, xn_l, CC, 0, w_h, w_l, CC, 0,
            nullptr, q_h, q_l, CC, 0, CC);
        gemm_bf16x3<1><<<grid, 256, SMEM_BYTES>>>(
            xn_h, xn_l, CC, 0, w_h + (size_t)CC * CC, w_l + (size_t)CC * CC, CC, 0,
            nullptr, k_h, k_l, CC, 0, CC);
        // V projection, transposed out: Vt[d][m], row stride NTOT
        gemm_bf16x3<2><<<grid, 256, SMEM_BYTES>>>(
            xn_h, xn_l, CC, 0, w_h + (size_t)2 * CC * CC, w_l + (size_t)2 * CC * CC, CC, 0,
            nullptr, vt_h, vt_l, NTOT, 0, CC);
    }

    // K3: S = Q @ K^T per batch (M=N=2304, K=192), fp32 out
    {
        dim3 grid(HW / BM, HW / BN, BB);
        gemm_bf16x3<0><<<grid, 256, SMEM_BYTES>>>(
            q_h, q_l, CC, (size_t)HW * CC,
            k_h, k_l, CC, (size_t)HW * CC,
            s, nullptr, nullptr, HW, (size_t)HW * HW, CC);
    }

    // K4: blend (softmax + relu^2), writes attn hi/lo bf16 in place
    blend_kernel<<<dim3(NTOT), 256>>>(s, w1, w2);

    // K5: out = attn @ V per batch (M=2304, N=192, K=2304)
    // attn rows: hi at [0,2304) halves, lo at [2304,4608), row stride 2*HW
    {
        dim3 grid(HW / BM, CC / BN, BB);
        const bf16* a_h = (const bf16*)s;
        const bf16* a_l = (const bf16*)s + HW;
        gemm_bf16x3<0><<<grid, 256, SMEM_BYTES>>>(
            a_h, a_l, 2 * HW, (size_t)HW * 2 * HW,
            vt_h, vt_l, NTOT, (size_t)HW,
            o, nullptr, nullptr, CC, (size_t)HW * CC, HW);
    }

    // K6: transpose back + residual
    out_transpose_kernel<<<dim3(HW / 32, CC / 32, BB), 256>>>(o, x, out);
}